// round 10
// baseline (speedup 1.0000x reference)
#include <cuda_runtime.h>
#include <cuda_bf16.h>
#include <math.h>
#include <stdint.h>

// Problem constants
#define BB   16
#define SS   512
#define SS0  511
#define DD   512
#define HGH  256
#define HEH  256
#define TT   128
#define MM   32
#define NN   (BB*SS)   // 8192

// Edge kernel geometry
#define EROWS 32               // rows per CTA -> 256 CTAs, 2 CTAs/SM
#define AST   132              // state row stride (u32 words)
#define BSTW  296              // B chunk row stride (u32 words)
#define CHK2  16               // k2-rows per chunk (K=32)
#define CH_WORDS (CHK2*BSTW)   // 4736 u32 per chunk
#define CH_BYTES (CH_WORDS*4)  // 18944 B
#define CH_UNITS (CH_WORDS/4)  // 1184 16B units
#define NBUF  3

// ---------------- device scratch ----------------
__device__ float  d_X   [NN*DD];
__device__ float  d_XW  [NN*HGH];
__device__ float  d_H0  [NN*HGH];
__device__ float  d_GS  [NN*HGH];
__device__ float  d_probs[MM*NN];

__device__ float    d_WT_ih0g[DD*HGH];
__device__ float    d_WT_ih1g[HGH*HGH];
__device__ uint32_t d_Bsw[24*CH_WORDS];    // 24 packed bf16 B chunks (3 mats x 8)
__device__ float    d_WT_head[HGH*TT];
__device__ float    d_WT_dep [HGH*TT];

// ---------------- helpers ----------------
__device__ __forceinline__ float fast_tanh(float x) {
    float y;
    asm("tanh.approx.f32 %0, %1;" : "=f"(y) : "f"(x));
    return y;
}

__device__ __forceinline__ void mma_bf16(float c[4], const uint32_t a[4],
                                         uint32_t b0, uint32_t b1) {
    asm volatile("mma.sync.aligned.m16n8k16.row.col.f32.bf16.bf16.f32 "
        "{%0,%1,%2,%3},{%4,%5,%6,%7},{%8,%9},{%0,%1,%2,%3};"
        : "+f"(c[0]), "+f"(c[1]), "+f"(c[2]), "+f"(c[3])
        : "r"(a[0]), "r"(a[1]), "r"(a[2]), "r"(a[3]), "r"(b0), "r"(b1));
}

__device__ __forceinline__ uint32_t pack_bf16x2(float lo, float hi) {
    __nv_bfloat162 v = __floats2bfloat162_rn(lo, hi);
    return *reinterpret_cast<uint32_t*>(&v);
}

__device__ __forceinline__ uint32_t smem_u32(const void* p) {
    return (uint32_t)__cvta_generic_to_shared(p);
}

// ---------------- single fused prep kernel ----------------
__device__ __forceinline__ void prep_transpose(const float* __restrict__ in,
                                               float* __restrict__ out,
                                               int R, int C, int bx, int tid)
{
    int tilesC = C >> 5, tilesR = R >> 5;
    if (bx >= tilesC * tilesR) return;
    int c0 = (bx % tilesC) << 5;
    int r0 = (bx / tilesC) << 5;
    __shared__ float tile[32][33];
    int x = tid & 31, y = tid >> 5;
    #pragma unroll
    for (int dy = 0; dy < 32; dy += 8)
        tile[y + dy][x] = in[(size_t)(r0 + y + dy) * C + c0 + x];
    __syncthreads();
    #pragma unroll
    for (int dy = 0; dy < 32; dy += 8)
        out[(size_t)(c0 + y + dy) * R + r0 + x] = tile[x][y + dy];
}

__global__ void __launch_bounds__(256) prep_kernel(
    const float* __restrict__ input, const float* __restrict__ sent,
    const float* __restrict__ g_Wih0, const float* __restrict__ g_Wih1,
    const float* __restrict__ head_W, const float* __restrict__ dep_W,
    const float* __restrict__ e_Whh0, const float* __restrict__ e_Wih1,
    const float* __restrict__ e_Whh1,
    float* __restrict__ X,
    float* __restrict__ WTih0g, float* __restrict__ WTih1g,
    float* __restrict__ WThead, float* __restrict__ WTdep,
    uint32_t* __restrict__ Bsw)
{
    int task = blockIdx.y;
    int bx   = blockIdx.x;
    int tid  = threadIdx.x;
    if (task == 0) {
        int idx = bx * 256 + tid;
        int n  = idx >> 7;
        int k4 = idx & 127;
        int b = n >> 9, s = n & 511;
        float4 v;
        if (s == 0) v = ((const float4*)sent)[k4];
        else        v = ((const float4*)input)[(size_t)((b*SS0 + s - 1) << 7) + k4];
        ((float4*)X)[idx] = v;
    } else if (task == 1) {
        prep_transpose(g_Wih0, WTih0g, HGH, DD, bx, tid);
    } else if (task == 2) {
        prep_transpose(g_Wih1, WTih1g, HGH, HGH, bx, tid);
    } else if (task == 3) {
        prep_transpose(head_W, WThead, TT, HGH, bx, tid);
    } else if (task == 4) {
        prep_transpose(dep_W, WTdep, TT, HGH, bx, tid);
    } else {
        // pack e-weights into LDS128-friendly bf16 chunks:
        // word(chunk, k2l, n) = chunk*CH_WORDS + k2l*BSTW + (n&7)*36 + (n>>3)
        // chunks: 0-7 Whh0 | 8-15 Wih1 | 16-23 Whh1  (8 chunks of K=32 each)
        if (bx >= 384) return;
        int idx = bx * 256 + tid;     // over 3*256*128
        int seg = idx >> 15;
        int rem = idx & 32767;
        int n  = rem >> 7;
        int k2 = rem & 127;
        const float* W = (seg == 0) ? e_Whh0 : (seg == 1) ? e_Wih1 : e_Whh1;
        float2 v = *(const float2*)&W[(size_t)n * 256 + (k2 << 1)];
        int chunk = seg * 8 + (k2 >> 4);
        int k2l = k2 & 15;
        Bsw[chunk * CH_WORDS + k2l * BSTW + (n & 7) * 36 + (n >> 3)] =
            pack_bf16x2(v.x, v.y);
    }
}

// ---------------- g-RNN recurrence: 4-CTA cluster per batch ----------------
__global__ void __launch_bounds__(256, 1) __cluster_dims__(4, 1, 1)
scan_g_cluster(const float* __restrict__ XW,
               const float* __restrict__ Whh,
               float* __restrict__ Hout,
               const int* __restrict__ mask, int applyMask)
{
    __shared__ float hs[2][272];
    __shared__ alignas(8) unsigned long long mbar[2];

    int tid  = threadIdx.x;
    int rank = blockIdx.x & 3;
    int b    = blockIdx.x >> 2;
    int jl   = tid >> 2;
    int q    = tid & 3;
    int j    = rank * 64 + jl;

    float w[64];
    {
        const float4* ws = (const float4*)(Whh + (size_t)j * 256 + q * 64);
        #pragma unroll
        for (int i = 0; i < 16; i++) {
            float4 v = ws[i];
            w[4*i+0] = v.x; w[4*i+1] = v.y; w[4*i+2] = v.z; w[4*i+3] = v.w;
        }
    }

    hs[0][tid] = 0.0f; hs[1][tid] = 0.0f;
    if (tid < 16) { hs[0][256 + tid] = 0.0f; hs[1][256 + tid] = 0.0f; }

    uint32_t mbar_l[2] = { smem_u32(&mbar[0]), smem_u32(&mbar[1]) };
    if (tid == 0) {
        asm volatile("mbarrier.init.shared.b64 [%0], 1;" :: "r"(mbar_l[0]));
        asm volatile("mbarrier.init.shared.b64 [%0], 1;" :: "r"(mbar_l[1]));
    }
    __syncthreads();
    asm volatile("barrier.cluster.arrive.aligned;" ::: "memory");
    asm volatile("barrier.cluster.wait.aligned;"   ::: "memory");

    uint32_t rdata[2][4], rbar[2][4];
    if (q == 0) {
        uint32_t off = (uint32_t)(rank * 68 + jl) * 4u;
        uint32_t l0 = smem_u32(hs[0]) + off;
        uint32_t l1 = smem_u32(hs[1]) + off;
        #pragma unroll
        for (int c = 0; c < 4; c++) {
            asm("mapa.shared::cluster.u32 %0, %1, %2;" : "=r"(rdata[0][c]) : "r"(l0), "r"(c));
            asm("mapa.shared::cluster.u32 %0, %1, %2;" : "=r"(rdata[1][c]) : "r"(l1), "r"(c));
            asm("mapa.shared::cluster.u32 %0, %1, %2;" : "=r"(rbar[0][c]) : "r"(mbar_l[0]), "r"(c));
            asm("mapa.shared::cluster.u32 %0, %1, %2;" : "=r"(rbar[1][c]) : "r"(mbar_l[1]), "r"(c));
        }
    }

    float xw_cur = (q == 0) ? XW[(size_t)(b * SS) * 256 + j] : 0.0f;
    float mf_cur = 1.0f;
    int cur = 0;

    for (int t = 0; t < SS; t++) {
        float xw_next = 0.0f, mf_next = 1.0f;
        if (q == 0 && t + 1 < SS) {
            xw_next = XW[(size_t)(b * SS + t + 1) * 256 + j];
            if (applyMask) mf_next = (float)mask[b * SS0 + t];
        }

        const float4* hq = (const float4*)(hs[cur] + q * 68);
        float a0 = 0.0f, a1 = 0.0f, a2 = 0.0f, a3 = 0.0f;
        #pragma unroll
        for (int i = 0; i < 16; i++) {
            float4 h = hq[i];
            a0 = fmaf(w[4*i+0], h.x, a0);
            a1 = fmaf(w[4*i+1], h.y, a1);
            a2 = fmaf(w[4*i+2], h.z, a2);
            a3 = fmaf(w[4*i+3], h.w, a3);
        }
        float s = (a0 + a1) + (a2 + a3);
        s += __shfl_xor_sync(0xFFFFFFFFu, s, 1);
        s += __shfl_xor_sync(0xFFFFFFFFu, s, 2);

        float hn = 0.0f;
        if (q == 0) {
            hn = fast_tanh(xw_cur + s);
            Hout[(size_t)(b * SS + t) * 256 + j] = hn * mf_cur;
        }

        __syncthreads();

        int nb = t & 1;
        if (q == 0) {
            uint32_t hv = __float_as_uint(hn);
            #pragma unroll
            for (int c = 0; c < 4; c++) {
                asm volatile(
                    "st.async.shared::cluster.mbarrier::complete_tx::bytes.b32 [%0], %1, [%2];"
                    :: "r"(rdata[cur ^ 1][c]), "r"(hv), "r"(rbar[nb][c]) : "memory");
            }
        }
        if (tid == 0) {
            asm volatile(
                "mbarrier.arrive.expect_tx.release.cluster.shared::cta.b64 _, [%0], 1024;"
                :: "r"(mbar_l[nb]) : "memory");
        }
        {
            uint32_t par = (t >> 1) & 1;
            asm volatile(
                "{\n\t.reg .pred P1;\n"
                "WAITLP_%=:\n\t"
                "mbarrier.try_wait.parity.acquire.cluster.shared::cta.b64 P1, [%0], %1;\n\t"
                "@!P1 bra WAITLP_%=;\n\t}"
                :: "r"(mbar_l[nb]), "r"(par) : "memory");
        }

        xw_cur = xw_next;
        mf_cur = mf_next;
        cur ^= 1;
    }
}

// ---------------- generic tiled SIMT GEMM (input proj + tags) ----------------
__device__ __forceinline__ void gemm_tile_loop(const float* __restrict__ A,
                                               const float* __restrict__ B,
                                               int K, int J, int n0, int j0, int tid,
                                               float acc[4][4],
                                               float (*As)[64], float (*Bs)[64])
{
    int tx = tid & 15, ty = tid >> 4;
    for (int k0 = 0; k0 < K; k0 += 16) {
        __syncthreads();
        {
            int row = tid >> 2;
            int kb  = (tid & 3) << 2;
            float4 av = *(const float4*)&A[(size_t)(n0 + row) * K + k0 + kb];
            As[kb + 0][row] = av.x;
            As[kb + 1][row] = av.y;
            As[kb + 2][row] = av.z;
            As[kb + 3][row] = av.w;
        }
        {
            int row = tid >> 4;
            int cb  = (tid & 15) << 2;
            *(float4*)&Bs[row][cb] = *(const float4*)&B[(size_t)(k0 + row) * J + j0 + cb];
        }
        __syncthreads();
        #pragma unroll
        for (int kk = 0; kk < 16; kk++) {
            float4 a = *(const float4*)&As[kk][ty << 2];
            float4 b = *(const float4*)&Bs[kk][tx << 2];
            acc[0][0] = fmaf(a.x, b.x, acc[0][0]);
            acc[0][1] = fmaf(a.x, b.y, acc[0][1]);
            acc[0][2] = fmaf(a.x, b.z, acc[0][2]);
            acc[0][3] = fmaf(a.x, b.w, acc[0][3]);
            acc[1][0] = fmaf(a.y, b.x, acc[1][0]);
            acc[1][1] = fmaf(a.y, b.y, acc[1][1]);
            acc[1][2] = fmaf(a.y, b.z, acc[1][2]);
            acc[1][3] = fmaf(a.y, b.w, acc[1][3]);
            acc[2][0] = fmaf(a.z, b.x, acc[2][0]);
            acc[2][1] = fmaf(a.z, b.y, acc[2][1]);
            acc[2][2] = fmaf(a.z, b.z, acc[2][2]);
            acc[2][3] = fmaf(a.z, b.w, acc[2][3]);
            acc[3][0] = fmaf(a.w, b.x, acc[3][0]);
            acc[3][1] = fmaf(a.w, b.y, acc[3][1]);
            acc[3][2] = fmaf(a.w, b.z, acc[3][2]);
            acc[3][3] = fmaf(a.w, b.w, acc[3][3]);
        }
    }
}

// EPI: 0 = +b1+b2 ; 1 = elu(+b1)
template<int EPI>
__global__ void __launch_bounds__(256) gemm_kernel(const float* __restrict__ A,
                                                   const float* __restrict__ B,
                                                   const float* __restrict__ b1,
                                                   const float* __restrict__ b2,
                                                   float* __restrict__ C,
                                                   int K, int J)
{
    __shared__ float As[16][64];
    __shared__ float Bs[16][64];
    int tid = threadIdx.x;
    int n0 = blockIdx.x * 64;
    int j0 = blockIdx.y * 64;
    float acc[4][4] = {};
    gemm_tile_loop(A, B, K, J, n0, j0, tid, acc, As, Bs);

    int tx = tid & 15, ty = tid >> 4;
    int j_base = j0 + (tx << 2);
    #pragma unroll
    for (int i = 0; i < 4; i++) {
        int n = n0 + (ty << 2) + i;
        float r[4];
        #pragma unroll
        for (int l = 0; l < 4; l++) {
            int j = j_base + l;
            float x = acc[i][l];
            if (EPI == 0) {
                x += b1[j] + b2[j];
            } else {
                x += b1[j];
                x = (x > 0.0f) ? x : expm1f(x);
            }
            r[l] = x;
        }
        *(float4*)&C[(size_t)n * J + j_base] = make_float4(r[0], r[1], r[2], r[3]);
    }
}

// ---------------- fused edge scan: bf16 mma.sync, 32 rows/CTA, 2 CTAs/SM -----
__device__ __forceinline__ void edge_fill(uint32_t* bufp, const uint32_t* src, int tid)
{
    uint32_t dst = smem_u32(bufp);
    #pragma unroll
    for (int i = 0; i < 5; i++) {
        int u = tid + i * 256;
        if (u < CH_UNITS) {
            asm volatile("cp.async.cg.shared.global [%0], [%1], 16;"
                         :: "r"(dst + (uint32_t)u * 16u), "l"(src + u * 4));
        }
    }
    asm volatile("cp.async.commit_group;");
}

// One GEMM pass: nch chunks of K=32; A from hA0 (first n0ch chunks) then hA1.
__device__ __forceinline__ void edge_pass(
    uint32_t* __restrict__ Bbuf, const uint32_t* __restrict__ Bg, int nch,
    const uint32_t* __restrict__ hA0, const uint32_t* __restrict__ hA1, int n0ch,
    float acc[2][4][4], int cg, int gid, int tig, int tid)
{
    edge_fill(Bbuf, Bg, tid);
    edge_fill(Bbuf + CH_WORDS, Bg + CH_WORDS, tid);

    #pragma unroll 1
    for (int c = 0; c < nch; c++) {
        if (c + 1 < nch) asm volatile("cp.async.wait_group 1;" ::: "memory");
        else             asm volatile("cp.async.wait_group 0;" ::: "memory");
        __syncthreads();

        const uint32_t* hA = (c < n0ch) ? hA0 : hA1;
        int aBase = ((c < n0ch) ? c : (c - n0ch)) * CHK2;
        const uint32_t* Bb = Bbuf + (c % NBUF) * CH_WORDS;

        #pragma unroll
        for (int ks = 0; ks < 2; ks++) {
            uint32_t a[2][4];
            #pragma unroll
            for (int mt = 0; mt < 2; mt++) {
                int r0 = mt * 16 + gid;
                int kb = aBase + ks * 8 + tig;
                a[mt][0] = hA[r0 * AST + kb];
                a[mt][1] = hA[(r0 + 8) * AST + kb];
                a[mt][2] = hA[r0 * AST + kb + 4];
                a[mt][3] = hA[(r0 + 8) * AST + kb + 4];
            }
            // B fragments: 2x LDS.128 covering nt=0..3
            const uint4* b0p = (const uint4*)(Bb + (ks*8 + tig)     * BSTW + gid * 36 + cg * 4);
            const uint4* b1p = (const uint4*)(Bb + (ks*8 + tig + 4) * BSTW + gid * 36 + cg * 4);
            uint4 b0v = *b0p;
            uint4 b1v = *b1p;
            uint32_t b0a[4] = {b0v.x, b0v.y, b0v.z, b0v.w};
            uint32_t b1a[4] = {b1v.x, b1v.y, b1v.z, b1v.w};
            #pragma unroll
            for (int nt = 0; nt < 4; nt++) {
                mma_bf16(acc[0][nt], a[0], b0a[nt], b1a[nt]);
                mma_bf16(acc[1][nt], a[1], b0a[nt], b1a[nt]);
            }
        }
        if (c + 2 < nch)
            edge_fill(Bbuf + ((c + 2) % NBUF) * CH_WORDS, Bg + (c + 2) * CH_WORDS, tid);
    }
}

__global__ void __launch_bounds__(256, 2) edge_mma_kernel(
    const float* __restrict__ gs,
    const uint32_t* __restrict__ Bsw,       // 24 chunks
    const float* __restrict__ w0,
    const float* __restrict__ bih0, const float* __restrict__ bhh0,
    const float* __restrict__ bih1, const float* __restrict__ bhh1,
    const float* __restrict__ clsW, const float* __restrict__ clsb,
    float* __restrict__ probs)
{
    extern __shared__ uint32_t dyn[];
    uint32_t* Bbuf = dyn;                      // NBUF * CH_WORDS, 16B aligned
    uint32_t* hs0  = Bbuf + NBUF * CH_WORDS;   // 32*AST
    uint32_t* hs1  = hs0 + EROWS * AST;
    float* w0s = (float*)(hs1 + EROWS * AST);  // 256
    float* bc0 = w0s + 256;
    float* bc1 = bc0 + 256;
    float* clw = bc1 + 256;
    float* ps  = clw + 256;                    // 32
    __shared__ float s_clsb;

    int tid = threadIdx.x;
    int lane = tid & 31, warp = tid >> 5;
    int gid = lane >> 2, tig = lane & 3;
    int cg = warp;                 // each warp owns 32 N-cols
    int n0 = blockIdx.x * EROWS;

    w0s[tid] = w0[tid];
    bc0[tid] = bih0[tid] + bhh0[tid];
    bc1[tid] = bih1[tid] + bhh1[tid];
    clw[tid] = clsW[tid];
    if (tid == 0) s_clsb = clsb[0];

    // init: h0 = bf16(gs rows), h1 = 0, p = 1
    for (int i = tid; i < EROWS * 128; i += 256) {
        int r = i >> 7, c2 = i & 127;
        float2 v = *(const float2*)&gs[(size_t)(n0 + r) * 256 + (c2 << 1)];
        hs0[r * AST + c2] = pack_bf16x2(v.x, v.y);
        hs1[r * AST + c2] = 0u;
    }
    if (tid < EROWS) ps[tid] = 1.0f;
    __syncthreads();

    float acc[2][4][4];

    for (int m = 0; m < MM; m++) {
        // ---- GEMM1: acc = h0 @ Whh0^T ----
        #pragma unroll
        for (int mt = 0; mt < 2; mt++)
            #pragma unroll
            for (int nt = 0; nt < 4; nt++)
                #pragma unroll
                for (int q = 0; q < 4; q++) acc[mt][nt][q] = 0.0f;

        edge_pass(Bbuf, Bsw, 8, hs0, hs0, 8, acc, cg, gid, tig, tid);
        __syncthreads();

        // epilogue1: h0 = tanh(acc + p*w0 + bc0)
        #pragma unroll
        for (int mt = 0; mt < 2; mt++) {
            int r0 = mt * 16 + gid;
            int r1 = r0 + 8;
            float p0 = ps[r0], p1 = ps[r1];
            #pragma unroll
            for (int nt = 0; nt < 4; nt++) {
                int cb = cg * 32 + nt * 8 + tig * 2;
                float x0 = acc[mt][nt][0] + p0 * w0s[cb]     + bc0[cb];
                float x1 = acc[mt][nt][1] + p0 * w0s[cb + 1] + bc0[cb + 1];
                float x2 = acc[mt][nt][2] + p1 * w0s[cb]     + bc0[cb];
                float x3 = acc[mt][nt][3] + p1 * w0s[cb + 1] + bc0[cb + 1];
                hs0[r0 * AST + (cb >> 1)] = pack_bf16x2(fast_tanh(x0), fast_tanh(x1));
                hs0[r1 * AST + (cb >> 1)] = pack_bf16x2(fast_tanh(x2), fast_tanh(x3));
            }
        }
        __syncthreads();

        // ---- GEMM2: acc = h0_new @ Wih1^T (+ h1 @ Whh1^T when m>0) ----
        #pragma unroll
        for (int mt = 0; mt < 2; mt++)
            #pragma unroll
            for (int nt = 0; nt < 4; nt++)
                #pragma unroll
                for (int q = 0; q < 4; q++) acc[mt][nt][q] = 0.0f;

        int nch2 = (m == 0) ? 8 : 16;
        edge_pass(Bbuf, Bsw + 8 * CH_WORDS, nch2, hs0, hs1, 8, acc, cg, gid, tig, tid);
        __syncthreads();

        // epilogue2: h1 = tanh(acc + bc1)
        #pragma unroll
        for (int mt = 0; mt < 2; mt++) {
            int r0 = mt * 16 + gid;
            int r1 = r0 + 8;
            #pragma unroll
            for (int nt = 0; nt < 4; nt++) {
                int cb = cg * 32 + nt * 8 + tig * 2;
                float x0 = acc[mt][nt][0] + bc1[cb];
                float x1 = acc[mt][nt][1] + bc1[cb + 1];
                float x2 = acc[mt][nt][2] + bc1[cb];
                float x3 = acc[mt][nt][3] + bc1[cb + 1];
                hs1[r0 * AST + (cb >> 1)] = pack_bf16x2(fast_tanh(x0), fast_tanh(x1));
                hs1[r1 * AST + (cb >> 1)] = pack_bf16x2(fast_tanh(x2), fast_tanh(x3));
            }
        }
        __syncthreads();

        // ---- p = sigmoid(h1 . clsW + clsb); each warp owns 4 rows ----
        #pragma unroll
        for (int i = 0; i < 4; i++) {
            int r = warp * 4 + i;
            float s = 0.0f;
            #pragma unroll
            for (int k = 0; k < 4; k++) {
                int c2 = lane + k * 32;
                __nv_bfloat162 bv = *reinterpret_cast<const __nv_bfloat162*>(&hs1[r * AST + c2]);
                float2 fv = __bfloat1622float2(bv);
                s = fmaf(fv.x, clw[c2 * 2], fmaf(fv.y, clw[c2 * 2 + 1], s));
            }
            #pragma unroll
            for (int o = 16; o; o >>= 1) s += __shfl_xor_sync(0xFFFFFFFFu, s, o);
            if (lane == 0) {
                float p = 1.0f / (1.0f + expf(-(s + s_clsb)));
                ps[r] = p;
                probs[(size_t)m * NN + n0 + r] = p;
            }
        }
        __syncthreads();
    }
}

// ---------------- arc_logits assembly ----------------
__global__ void arc_kernel(const float* __restrict__ probs, float* __restrict__ arc)
{
    int j = blockIdx.x;
    int b = blockIdx.y;
    int i = threadIdx.x;
    int start = (i - MM > 0) ? (i - MM) : 0;
    float v = 0.0f;
    if (j >= start && j < i) {
        int midx = j - start;
        v = probs[(size_t)midx * NN + b * SS + i];
    }
    arc[(size_t)(b * SS + j) * SS + i] = v;
}

// ---------------- host orchestration ----------------
static const int EDGE_SMEM_BYTES =
    (NBUF * CH_WORDS + 2 * EROWS * AST) * 4 + (4 * 256 + 32) * 4 + 256;

extern "C" void kernel_launch(void* const* d_in, const int* in_sizes, int n_in,
                              void* d_out, int out_size)
{
    const float* input   = (const float*)d_in[0];
    const float* sentinel= (const float*)d_in[1];
    const float* g_Wih0  = (const float*)d_in[2];
    const float* g_Whh0  = (const float*)d_in[3];
    const float* g_bih0  = (const float*)d_in[4];
    const float* g_bhh0  = (const float*)d_in[5];
    const float* g_Wih1  = (const float*)d_in[6];
    const float* g_Whh1  = (const float*)d_in[7];
    const float* g_bih1  = (const float*)d_in[8];
    const float* g_bhh1  = (const float*)d_in[9];
    const float* e_Wih0  = (const float*)d_in[10];
    const float* e_Whh0  = (const float*)d_in[11];
    const float* e_bih0  = (const float*)d_in[12];
    const float* e_bhh0  = (const float*)d_in[13];
    const float* e_Wih1  = (const float*)d_in[14];
    const float* e_Whh1  = (const float*)d_in[15];
    const float* e_bih1  = (const float*)d_in[16];
    const float* e_bhh1  = (const float*)d_in[17];
    const float* cls_W   = (const float*)d_in[18];
    const float* cls_b   = (const float*)d_in[19];
    const float* head_W  = (const float*)d_in[20];
    const float* head_b  = (const float*)d_in[21];
    const float* dep_W   = (const float*)d_in[22];
    const float* dep_b   = (const float*)d_in[23];
    const int*   mask    = (const int*)  d_in[24];
    (void)in_sizes; (void)n_in; (void)out_size;

    float* out = (float*)d_out;
    float* out_head = out;
    float* out_dep  = out + (size_t)NN * TT;
    float* out_arc  = out + (size_t)2 * NN * TT;

    float *pX, *pXW, *pH0, *pGS, *pprobs;
    float *pWTih0g, *pWTih1g, *pWThead, *pWTdep;
    uint32_t *pBsw;
    cudaGetSymbolAddress((void**)&pX, d_X);
    cudaGetSymbolAddress((void**)&pXW, d_XW);
    cudaGetSymbolAddress((void**)&pH0, d_H0);
    cudaGetSymbolAddress((void**)&pGS, d_GS);
    cudaGetSymbolAddress((void**)&pprobs, d_probs);
    cudaGetSymbolAddress((void**)&pWTih0g, d_WT_ih0g);
    cudaGetSymbolAddress((void**)&pWTih1g, d_WT_ih1g);
    cudaGetSymbolAddress((void**)&pWThead, d_WT_head);
    cudaGetSymbolAddress((void**)&pWTdep, d_WT_dep);
    cudaGetSymbolAddress((void**)&pBsw, d_Bsw);

    cudaFuncSetAttribute(edge_mma_kernel,
                         cudaFuncAttributeMaxDynamicSharedMemorySize, EDGE_SMEM_BYTES);

    // launch 1: fused prep
    prep_kernel<<<dim3(4096, 6), 256>>>(
        input, sentinel, g_Wih0, g_Wih1, head_W, dep_W,
        e_Whh0, e_Wih1, e_Whh1,
        pX, pWTih0g, pWTih1g, pWThead, pWTdep, pBsw);

    // launches 2-5: g-RNN layers
    gemm_kernel<0><<<dim3(NN/64, HGH/64), 256>>>(pX, pWTih0g, g_bih0, g_bhh0, pXW, DD, HGH);
    scan_g_cluster<<<BB*4, 256>>>(pXW, g_Whh0, pH0, nullptr, 0);
    gemm_kernel<0><<<dim3(NN/64, HGH/64), 256>>>(pH0, pWTih1g, g_bih1, g_bhh1, pXW, HGH, HGH);
    scan_g_cluster<<<BB*4, 256>>>(pXW, g_Whh1, pGS, mask, 1);

    // launch 6: fused edge scan (bf16 mma.sync, 2 CTAs/SM)
    edge_mma_kernel<<<NN/EROWS, 256, EDGE_SMEM_BYTES>>>(
        pGS, pBsw, e_Wih0, e_bih0, e_bhh0, e_bih1, e_bhh1,
        cls_W, cls_b, pprobs);

    // tags
    gemm_kernel<1><<<dim3(NN/64, TT/64), 256>>>(pGS, pWThead, head_b, nullptr, out_head, HGH, TT);
    gemm_kernel<1><<<dim3(NN/64, TT/64), 256>>>(pGS, pWTdep,  dep_b,  nullptr, out_dep,  HGH, TT);

    // arc_logits
    arc_kernel<<<dim3(SS, BB), SS>>>(pprobs, out_arc);
}

// round 11
// speedup vs baseline: 1.0375x; 1.0375x over previous
#include <cuda_runtime.h>
#include <cuda_bf16.h>
#include <math.h>
#include <stdint.h>

// Problem constants
#define BB   16
#define SS   512
#define SS0  511
#define DD   512
#define HGH  256
#define HEH  256
#define TT   128
#define MM   32
#define NN   (BB*SS)   // 8192

// Edge kernel geometry (R5 geometry + ldmatrix/LDS128 fragment path)
#define EROWS 64               // rows per CTA -> 128 CTAs, 1 CTA/SM
#define AST   132              // state row stride (u32 words)
#define BSTW  296              // B chunk row stride (u32 words)
#define CHK2  32               // k2-rows per chunk (K=64)
#define CH_WORDS (CHK2*BSTW)   // 9472 u32 per chunk
#define CH_UNITS (CH_WORDS/4)  // 2368 16B units
#define NBUF  3

// ---------------- device scratch ----------------
__device__ float  d_X   [NN*DD];
__device__ float  d_XW  [NN*HGH];
__device__ float  d_H0  [NN*HGH];
__device__ float  d_GS  [NN*HGH];
__device__ float  d_probs[MM*NN];

__device__ float    d_WT_ih0g[DD*HGH];
__device__ float    d_WT_ih1g[HGH*HGH];
__device__ __align__(16) uint32_t d_Bsw[12*CH_WORDS];  // 12 packed bf16 B chunks
__device__ float    d_WT_head[HGH*TT];
__device__ float    d_WT_dep [HGH*TT];

// ---------------- helpers ----------------
__device__ __forceinline__ float fast_tanh(float x) {
    float y;
    asm("tanh.approx.f32 %0, %1;" : "=f"(y) : "f"(x));
    return y;
}

__device__ __forceinline__ void mma_bf16(float c[4], const uint32_t a[4],
                                         uint32_t b0, uint32_t b1) {
    asm volatile("mma.sync.aligned.m16n8k16.row.col.f32.bf16.bf16.f32 "
        "{%0,%1,%2,%3},{%4,%5,%6,%7},{%8,%9},{%0,%1,%2,%3};"
        : "+f"(c[0]), "+f"(c[1]), "+f"(c[2]), "+f"(c[3])
        : "r"(a[0]), "r"(a[1]), "r"(a[2]), "r"(a[3]), "r"(b0), "r"(b1));
}

__device__ __forceinline__ uint32_t pack_bf16x2(float lo, float hi) {
    __nv_bfloat162 v = __floats2bfloat162_rn(lo, hi);
    return *reinterpret_cast<uint32_t*>(&v);
}

__device__ __forceinline__ uint32_t smem_u32(const void* p) {
    return (uint32_t)__cvta_generic_to_shared(p);
}

// ---------------- single fused prep kernel ----------------
__device__ __forceinline__ void prep_transpose(const float* __restrict__ in,
                                               float* __restrict__ out,
                                               int R, int C, int bx, int tid)
{
    int tilesC = C >> 5, tilesR = R >> 5;
    if (bx >= tilesC * tilesR) return;
    int c0 = (bx % tilesC) << 5;
    int r0 = (bx / tilesC) << 5;
    __shared__ float tile[32][33];
    int x = tid & 31, y = tid >> 5;
    #pragma unroll
    for (int dy = 0; dy < 32; dy += 8)
        tile[y + dy][x] = in[(size_t)(r0 + y + dy) * C + c0 + x];
    __syncthreads();
    #pragma unroll
    for (int dy = 0; dy < 32; dy += 8)
        out[(size_t)(c0 + y + dy) * R + r0 + x] = tile[x][y + dy];
}

__global__ void __launch_bounds__(256) prep_kernel(
    const float* __restrict__ input, const float* __restrict__ sent,
    const float* __restrict__ g_Wih0, const float* __restrict__ g_Wih1,
    const float* __restrict__ head_W, const float* __restrict__ dep_W,
    const float* __restrict__ e_Whh0, const float* __restrict__ e_Wih1,
    const float* __restrict__ e_Whh1,
    float* __restrict__ X,
    float* __restrict__ WTih0g, float* __restrict__ WTih1g,
    float* __restrict__ WThead, float* __restrict__ WTdep,
    uint32_t* __restrict__ Bsw)
{
    int task = blockIdx.y;
    int bx   = blockIdx.x;
    int tid  = threadIdx.x;
    if (task == 0) {
        int idx = bx * 256 + tid;
        int n  = idx >> 7;
        int k4 = idx & 127;
        int b = n >> 9, s = n & 511;
        float4 v;
        if (s == 0) v = ((const float4*)sent)[k4];
        else        v = ((const float4*)input)[(size_t)((b*SS0 + s - 1) << 7) + k4];
        ((float4*)X)[idx] = v;
    } else if (task == 1) {
        prep_transpose(g_Wih0, WTih0g, HGH, DD, bx, tid);
    } else if (task == 2) {
        prep_transpose(g_Wih1, WTih1g, HGH, HGH, bx, tid);
    } else if (task == 3) {
        prep_transpose(head_W, WThead, TT, HGH, bx, tid);
    } else if (task == 4) {
        prep_transpose(dep_W, WTdep, TT, HGH, bx, tid);
    } else {
        // pack e-weights: word(chunk, k2l, n) = chunk*CH_WORDS + k2l*BSTW + (n&7)*36 + (n>>3)
        // chunks (K=64 each): 0-3 Whh0 | 4-7 Wih1 | 8-11 Whh1
        if (bx >= 384) return;
        int idx = bx * 256 + tid;     // over 3*256*128
        int seg = idx >> 15;
        int rem = idx & 32767;
        int n  = rem >> 7;
        int k2 = rem & 127;
        const float* W = (seg == 0) ? e_Whh0 : (seg == 1) ? e_Wih1 : e_Whh1;
        float2 v = *(const float2*)&W[(size_t)n * 256 + (k2 << 1)];
        int chunk = seg * 4 + (k2 >> 5);
        int k2l = k2 & 31;
        Bsw[chunk * CH_WORDS + k2l * BSTW + (n & 7) * 36 + (n >> 3)] =
            pack_bf16x2(v.x, v.y);
    }
}

// ---------------- g-RNN recurrence: 4-CTA cluster per batch ----------------
__global__ void __launch_bounds__(256, 1) __cluster_dims__(4, 1, 1)
scan_g_cluster(const float* __restrict__ XW,
               const float* __restrict__ Whh,
               float* __restrict__ Hout,
               const int* __restrict__ mask, int applyMask)
{
    __shared__ float hs[2][272];
    __shared__ alignas(8) unsigned long long mbar[2];

    int tid  = threadIdx.x;
    int rank = blockIdx.x & 3;
    int b    = blockIdx.x >> 2;
    int jl   = tid >> 2;
    int q    = tid & 3;
    int j    = rank * 64 + jl;

    float w[64];
    {
        const float4* ws = (const float4*)(Whh + (size_t)j * 256 + q * 64);
        #pragma unroll
        for (int i = 0; i < 16; i++) {
            float4 v = ws[i];
            w[4*i+0] = v.x; w[4*i+1] = v.y; w[4*i+2] = v.z; w[4*i+3] = v.w;
        }
    }

    hs[0][tid] = 0.0f; hs[1][tid] = 0.0f;
    if (tid < 16) { hs[0][256 + tid] = 0.0f; hs[1][256 + tid] = 0.0f; }

    uint32_t mbar_l[2] = { smem_u32(&mbar[0]), smem_u32(&mbar[1]) };
    if (tid == 0) {
        asm volatile("mbarrier.init.shared.b64 [%0], 1;" :: "r"(mbar_l[0]));
        asm volatile("mbarrier.init.shared.b64 [%0], 1;" :: "r"(mbar_l[1]));
    }
    __syncthreads();
    asm volatile("barrier.cluster.arrive.aligned;" ::: "memory");
    asm volatile("barrier.cluster.wait.aligned;"   ::: "memory");

    uint32_t rdata[2][4], rbar[2][4];
    if (q == 0) {
        uint32_t off = (uint32_t)(rank * 68 + jl) * 4u;
        uint32_t l0 = smem_u32(hs[0]) + off;
        uint32_t l1 = smem_u32(hs[1]) + off;
        #pragma unroll
        for (int c = 0; c < 4; c++) {
            asm("mapa.shared::cluster.u32 %0, %1, %2;" : "=r"(rdata[0][c]) : "r"(l0), "r"(c));
            asm("mapa.shared::cluster.u32 %0, %1, %2;" : "=r"(rdata[1][c]) : "r"(l1), "r"(c));
            asm("mapa.shared::cluster.u32 %0, %1, %2;" : "=r"(rbar[0][c]) : "r"(mbar_l[0]), "r"(c));
            asm("mapa.shared::cluster.u32 %0, %1, %2;" : "=r"(rbar[1][c]) : "r"(mbar_l[1]), "r"(c));
        }
    }

    float xw_cur = (q == 0) ? XW[(size_t)(b * SS) * 256 + j] : 0.0f;
    float mf_cur = 1.0f;
    int cur = 0;

    for (int t = 0; t < SS; t++) {
        float xw_next = 0.0f, mf_next = 1.0f;
        if (q == 0 && t + 1 < SS) {
            xw_next = XW[(size_t)(b * SS + t + 1) * 256 + j];
            if (applyMask) mf_next = (float)mask[b * SS0 + t];
        }

        const float4* hq = (const float4*)(hs[cur] + q * 68);
        float a0 = 0.0f, a1 = 0.0f, a2 = 0.0f, a3 = 0.0f;
        #pragma unroll
        for (int i = 0; i < 16; i++) {
            float4 h = hq[i];
            a0 = fmaf(w[4*i+0], h.x, a0);
            a1 = fmaf(w[4*i+1], h.y, a1);
            a2 = fmaf(w[4*i+2], h.z, a2);
            a3 = fmaf(w[4*i+3], h.w, a3);
        }
        float s = (a0 + a1) + (a2 + a3);
        s += __shfl_xor_sync(0xFFFFFFFFu, s, 1);
        s += __shfl_xor_sync(0xFFFFFFFFu, s, 2);

        float hn = 0.0f;
        if (q == 0) {
            hn = fast_tanh(xw_cur + s);
            Hout[(size_t)(b * SS + t) * 256 + j] = hn * mf_cur;
        }

        __syncthreads();

        int nb = t & 1;
        if (q == 0) {
            uint32_t hv = __float_as_uint(hn);
            #pragma unroll
            for (int c = 0; c < 4; c++) {
                asm volatile(
                    "st.async.shared::cluster.mbarrier::complete_tx::bytes.b32 [%0], %1, [%2];"
                    :: "r"(rdata[cur ^ 1][c]), "r"(hv), "r"(rbar[nb][c]) : "memory");
            }
        }
        if (tid == 0) {
            asm volatile(
                "mbarrier.arrive.expect_tx.release.cluster.shared::cta.b64 _, [%0], 1024;"
                :: "r"(mbar_l[nb]) : "memory");
        }
        {
            uint32_t par = (t >> 1) & 1;
            asm volatile(
                "{\n\t.reg .pred P1;\n"
                "WAITLP_%=:\n\t"
                "mbarrier.try_wait.parity.acquire.cluster.shared::cta.b64 P1, [%0], %1;\n\t"
                "@!P1 bra WAITLP_%=;\n\t}"
                :: "r"(mbar_l[nb]), "r"(par) : "memory");
        }

        xw_cur = xw_next;
        mf_cur = mf_next;
        cur ^= 1;
    }
}

// ---------------- generic tiled SIMT GEMM (input proj + tags) ----------------
__device__ __forceinline__ void gemm_tile_loop(const float* __restrict__ A,
                                               const float* __restrict__ B,
                                               int K, int J, int n0, int j0, int tid,
                                               float acc[4][4],
                                               float (*As)[64], float (*Bs)[64])
{
    int tx = tid & 15, ty = tid >> 4;
    for (int k0 = 0; k0 < K; k0 += 16) {
        __syncthreads();
        {
            int row = tid >> 2;
            int kb  = (tid & 3) << 2;
            float4 av = *(const float4*)&A[(size_t)(n0 + row) * K + k0 + kb];
            As[kb + 0][row] = av.x;
            As[kb + 1][row] = av.y;
            As[kb + 2][row] = av.z;
            As[kb + 3][row] = av.w;
        }
        {
            int row = tid >> 4;
            int cb  = (tid & 15) << 2;
            *(float4*)&Bs[row][cb] = *(const float4*)&B[(size_t)(k0 + row) * J + j0 + cb];
        }
        __syncthreads();
        #pragma unroll
        for (int kk = 0; kk < 16; kk++) {
            float4 a = *(const float4*)&As[kk][ty << 2];
            float4 b = *(const float4*)&Bs[kk][tx << 2];
            acc[0][0] = fmaf(a.x, b.x, acc[0][0]);
            acc[0][1] = fmaf(a.x, b.y, acc[0][1]);
            acc[0][2] = fmaf(a.x, b.z, acc[0][2]);
            acc[0][3] = fmaf(a.x, b.w, acc[0][3]);
            acc[1][0] = fmaf(a.y, b.x, acc[1][0]);
            acc[1][1] = fmaf(a.y, b.y, acc[1][1]);
            acc[1][2] = fmaf(a.y, b.z, acc[1][2]);
            acc[1][3] = fmaf(a.y, b.w, acc[1][3]);
            acc[2][0] = fmaf(a.z, b.x, acc[2][0]);
            acc[2][1] = fmaf(a.z, b.y, acc[2][1]);
            acc[2][2] = fmaf(a.z, b.z, acc[2][2]);
            acc[2][3] = fmaf(a.z, b.w, acc[2][3]);
            acc[3][0] = fmaf(a.w, b.x, acc[3][0]);
            acc[3][1] = fmaf(a.w, b.y, acc[3][1]);
            acc[3][2] = fmaf(a.w, b.z, acc[3][2]);
            acc[3][3] = fmaf(a.w, b.w, acc[3][3]);
        }
    }
}

// EPI: 0 = +b1+b2 ; 1 = elu(+b1)
template<int EPI>
__global__ void __launch_bounds__(256) gemm_kernel(const float* __restrict__ A,
                                                   const float* __restrict__ B,
                                                   const float* __restrict__ b1,
                                                   const float* __restrict__ b2,
                                                   float* __restrict__ C,
                                                   int K, int J)
{
    __shared__ float As[16][64];
    __shared__ float Bs[16][64];
    int tid = threadIdx.x;
    int n0 = blockIdx.x * 64;
    int j0 = blockIdx.y * 64;
    float acc[4][4] = {};
    gemm_tile_loop(A, B, K, J, n0, j0, tid, acc, As, Bs);

    int tx = tid & 15, ty = tid >> 4;
    int j_base = j0 + (tx << 2);
    #pragma unroll
    for (int i = 0; i < 4; i++) {
        int n = n0 + (ty << 2) + i;
        float r[4];
        #pragma unroll
        for (int l = 0; l < 4; l++) {
            int j = j_base + l;
            float x = acc[i][l];
            if (EPI == 0) {
                x += b1[j] + b2[j];
            } else {
                x += b1[j];
                x = (x > 0.0f) ? x : expm1f(x);
            }
            r[l] = x;
        }
        *(float4*)&C[(size_t)n * J + j_base] = make_float4(r[0], r[1], r[2], r[3]);
    }
}

// ---------------- fused edge scan: bf16 mma.sync + ldmatrix + LDS.128 --------
__device__ __forceinline__ void edge_fill(uint32_t* bufp, const uint32_t* src, int tid)
{
    uint32_t dst = smem_u32(bufp);
    #pragma unroll
    for (int i = 0; i < 10; i++) {
        int u = tid + i * 256;
        if (u < CH_UNITS) {
            asm volatile("cp.async.cg.shared.global [%0], [%1], 16;"
                         :: "r"(dst + (uint32_t)u * 16u), "l"(src + u * 4));
        }
    }
    asm volatile("cp.async.commit_group;");
}

// One GEMM pass: nch K=64 chunks; A from hA0 (first n0ch) then hA1.
__device__ __forceinline__ void edge_pass(
    uint32_t* __restrict__ Bbuf, const uint32_t* __restrict__ Bg, int nch,
    const uint32_t* __restrict__ hA0, const uint32_t* __restrict__ hA1, int n0ch,
    float acc[2][8][4], int rg, int cg, int lane, int tid)
{
    edge_fill(Bbuf, Bg, tid);
    if (nch > 1) edge_fill(Bbuf + CH_WORDS, Bg + CH_WORDS, tid);

    int m4 = lane >> 3;          // ldmatrix matrix index
    int rr = lane & 7;
    int gid = lane >> 2, tig = lane & 3;
    uint32_t rowoff[2];
    #pragma unroll
    for (int mt = 0; mt < 2; mt++) {
        int row = rg * 32 + mt * 16 + (m4 & 1) * 8 + rr;
        rowoff[mt] = (uint32_t)(row * AST + (m4 >> 1) * 4) * 4u;
    }

    #pragma unroll 1
    for (int c = 0; c < nch; c++) {
        if (c + 1 < nch) asm volatile("cp.async.wait_group 1;" ::: "memory");
        else             asm volatile("cp.async.wait_group 0;" ::: "memory");
        __syncthreads();
        if (c + 2 < nch)
            edge_fill(Bbuf + ((c + 2) % NBUF) * CH_WORDS, Bg + (c + 2) * CH_WORDS, tid);

        const uint32_t* hA = (c < n0ch) ? hA0 : hA1;
        uint32_t hBase = smem_u32(hA) + (uint32_t)(((c < n0ch) ? c : c - n0ch) * 32) * 4u;
        const uint32_t* Bb = Bbuf + (c % NBUF) * CH_WORDS;

        #pragma unroll
        for (int s = 0; s < 4; s++) {
            uint32_t a[2][4];
            #pragma unroll
            for (int mt = 0; mt < 2; mt++) {
                uint32_t addr = hBase + rowoff[mt] + (uint32_t)(s * 8) * 4u;
                asm volatile("ldmatrix.sync.aligned.m8n8.x4.shared.b16 {%0,%1,%2,%3}, [%4];"
                    : "=r"(a[mt][0]), "=r"(a[mt][1]), "=r"(a[mt][2]), "=r"(a[mt][3])
                    : "r"(addr));
            }
            const uint4* b0p = (const uint4*)(Bb + (s*8 + tig)     * BSTW + gid * 36 + cg * 8);
            const uint4* b1p = (const uint4*)(Bb + (s*8 + tig + 4) * BSTW + gid * 36 + cg * 8);
            uint4 B0l = b0p[0], B0h = b0p[1];
            uint4 B1l = b1p[0], B1h = b1p[1];
            uint32_t b0a[8] = {B0l.x,B0l.y,B0l.z,B0l.w, B0h.x,B0h.y,B0h.z,B0h.w};
            uint32_t b1a[8] = {B1l.x,B1l.y,B1l.z,B1l.w, B1h.x,B1h.y,B1h.z,B1h.w};
            #pragma unroll
            for (int nt = 0; nt < 8; nt++) {
                mma_bf16(acc[0][nt], a[0], b0a[nt], b1a[nt]);
                mma_bf16(acc[1][nt], a[1], b0a[nt], b1a[nt]);
            }
        }
    }
}

__global__ void __launch_bounds__(256, 1) edge_mma_kernel(
    const float* __restrict__ gs,
    const uint32_t* __restrict__ Bsw,       // 12 chunks
    const float* __restrict__ w0,
    const float* __restrict__ bih0, const float* __restrict__ bhh0,
    const float* __restrict__ bih1, const float* __restrict__ bhh1,
    const float* __restrict__ clsW, const float* __restrict__ clsb,
    float* __restrict__ probs)
{
    extern __shared__ uint32_t dyn[];
    uint32_t* Bbuf = dyn;                      // NBUF * CH_WORDS (16B aligned)
    uint32_t* hs0  = Bbuf + NBUF * CH_WORDS;   // 64*AST
    uint32_t* hs1  = hs0 + EROWS * AST;
    float* w0s = (float*)(hs1 + EROWS * AST);  // 256
    float* bc0 = w0s + 256;
    float* bc1 = bc0 + 256;
    float* clw = bc1 + 256;
    float* ps  = clw + 256;                    // 64
    __shared__ float s_clsb;

    int tid = threadIdx.x;
    int lane = tid & 31, warp = tid >> 5;
    int gid = lane >> 2, tig = lane & 3;
    int rg = warp >> 2, cg = warp & 3;
    int n0 = blockIdx.x * EROWS;

    w0s[tid] = w0[tid];
    bc0[tid] = bih0[tid] + bhh0[tid];
    bc1[tid] = bih1[tid] + bhh1[tid];
    clw[tid] = clsW[tid];
    if (tid == 0) s_clsb = clsb[0];

    // init: h0 = bf16(gs rows), h1 = 0, p = 1
    for (int i = tid; i < EROWS * 128; i += 256) {
        int r = i >> 7, c2 = i & 127;
        float2 v = *(const float2*)&gs[(size_t)(n0 + r) * 256 + (c2 << 1)];
        hs0[r * AST + c2] = pack_bf16x2(v.x, v.y);
        hs1[r * AST + c2] = 0u;
    }
    if (tid < EROWS) ps[tid] = 1.0f;
    __syncthreads();

    float acc[2][8][4];

    for (int m = 0; m < MM; m++) {
        // ---- GEMM1: acc = h0 @ Whh0^T (chunks 0-3) ----
        #pragma unroll
        for (int mt = 0; mt < 2; mt++)
            #pragma unroll
            for (int nt = 0; nt < 8; nt++)
                #pragma unroll
                for (int q = 0; q < 4; q++) acc[mt][nt][q] = 0.0f;

        edge_pass(Bbuf, Bsw, 4, hs0, hs0, 4, acc, rg, cg, lane, tid);
        __syncthreads();

        // epilogue1: h0 = tanh(acc + p*w0 + bc0)
        #pragma unroll
        for (int mt = 0; mt < 2; mt++) {
            int r0 = rg * 32 + mt * 16 + gid;
            int r1 = r0 + 8;
            float p0 = ps[r0], p1 = ps[r1];
            #pragma unroll
            for (int nt = 0; nt < 8; nt++) {
                int cb = cg * 64 + nt * 8 + tig * 2;
                float x0 = acc[mt][nt][0] + p0 * w0s[cb]     + bc0[cb];
                float x1 = acc[mt][nt][1] + p0 * w0s[cb + 1] + bc0[cb + 1];
                float x2 = acc[mt][nt][2] + p1 * w0s[cb]     + bc0[cb];
                float x3 = acc[mt][nt][3] + p1 * w0s[cb + 1] + bc0[cb + 1];
                hs0[r0 * AST + (cb >> 1)] = pack_bf16x2(fast_tanh(x0), fast_tanh(x1));
                hs0[r1 * AST + (cb >> 1)] = pack_bf16x2(fast_tanh(x2), fast_tanh(x3));
            }
        }
        __syncthreads();

        // ---- GEMM2: acc = h0_new @ Wih1^T (+ h1 @ Whh1^T when m>0) ----
        #pragma unroll
        for (int mt = 0; mt < 2; mt++)
            #pragma unroll
            for (int nt = 0; nt < 8; nt++)
                #pragma unroll
                for (int q = 0; q < 4; q++) acc[mt][nt][q] = 0.0f;

        int nch2 = (m == 0) ? 4 : 8;
        edge_pass(Bbuf, Bsw + 4 * CH_WORDS, nch2, hs0, hs1, 4, acc, rg, cg, lane, tid);
        __syncthreads();

        // epilogue2: h1 = tanh(acc + bc1)
        #pragma unroll
        for (int mt = 0; mt < 2; mt++) {
            int r0 = rg * 32 + mt * 16 + gid;
            int r1 = r0 + 8;
            #pragma unroll
            for (int nt = 0; nt < 8; nt++) {
                int cb = cg * 64 + nt * 8 + tig * 2;
                float x0 = acc[mt][nt][0] + bc1[cb];
                float x1 = acc[mt][nt][1] + bc1[cb + 1];
                float x2 = acc[mt][nt][2] + bc1[cb];
                float x3 = acc[mt][nt][3] + bc1[cb + 1];
                hs1[r0 * AST + (cb >> 1)] = pack_bf16x2(fast_tanh(x0), fast_tanh(x1));
                hs1[r1 * AST + (cb >> 1)] = pack_bf16x2(fast_tanh(x2), fast_tanh(x3));
            }
        }
        __syncthreads();

        // ---- p = sigmoid(h1 . clsW + clsb); each warp owns 8 rows ----
        #pragma unroll
        for (int i = 0; i < 8; i++) {
            int r = warp * 8 + i;
            float s = 0.0f;
            #pragma unroll
            for (int k = 0; k < 4; k++) {
                int c2 = lane + k * 32;
                __nv_bfloat162 bv = *reinterpret_cast<const __nv_bfloat162*>(&hs1[r * AST + c2]);
                float2 fv = __bfloat1622float2(bv);
                s = fmaf(fv.x, clw[c2 * 2], fmaf(fv.y, clw[c2 * 2 + 1], s));
            }
            #pragma unroll
            for (int o = 16; o; o >>= 1) s += __shfl_xor_sync(0xFFFFFFFFu, s, o);
            if (lane == 0) {
                float p = 1.0f / (1.0f + expf(-(s + s_clsb)));
                ps[r] = p;
                probs[(size_t)m * NN + n0 + r] = p;
            }
        }
        __syncthreads();
    }
}

// ---------------- arc_logits assembly ----------------
__global__ void arc_kernel(const float* __restrict__ probs, float* __restrict__ arc)
{
    int j = blockIdx.x;
    int b = blockIdx.y;
    int i = threadIdx.x;
    int start = (i - MM > 0) ? (i - MM) : 0;
    float v = 0.0f;
    if (j >= start && j < i) {
        int midx = j - start;
        v = probs[(size_t)midx * NN + b * SS + i];
    }
    arc[(size_t)(b * SS + j) * SS + i] = v;
}

// ---------------- host orchestration ----------------
static const int EDGE_SMEM_BYTES =
    (NBUF * CH_WORDS + 2 * EROWS * AST) * 4 + (4 * 256 + EROWS) * 4 + 256;

extern "C" void kernel_launch(void* const* d_in, const int* in_sizes, int n_in,
                              void* d_out, int out_size)
{
    const float* input   = (const float*)d_in[0];
    const float* sentinel= (const float*)d_in[1];
    const float* g_Wih0  = (const float*)d_in[2];
    const float* g_Whh0  = (const float*)d_in[3];
    const float* g_bih0  = (const float*)d_in[4];
    const float* g_bhh0  = (const float*)d_in[5];
    const float* g_Wih1  = (const float*)d_in[6];
    const float* g_Whh1  = (const float*)d_in[7];
    const float* g_bih1  = (const float*)d_in[8];
    const float* g_bhh1  = (const float*)d_in[9];
    const float* e_Wih0  = (const float*)d_in[10];
    const float* e_Whh0  = (const float*)d_in[11];
    const float* e_bih0  = (const float*)d_in[12];
    const float* e_bhh0  = (const float*)d_in[13];
    const float* e_Wih1  = (const float*)d_in[14];
    const float* e_Whh1  = (const float*)d_in[15];
    const float* e_bih1  = (const float*)d_in[16];
    const float* e_bhh1  = (const float*)d_in[17];
    const float* cls_W   = (const float*)d_in[18];
    const float* cls_b   = (const float*)d_in[19];
    const float* head_W  = (const float*)d_in[20];
    const float* head_b  = (const float*)d_in[21];
    const float* dep_W   = (const float*)d_in[22];
    const float* dep_b   = (const float*)d_in[23];
    const int*   mask    = (const int*)  d_in[24];
    (void)in_sizes; (void)n_in; (void)out_size;

    float* out = (float*)d_out;
    float* out_head = out;
    float* out_dep  = out + (size_t)NN * TT;
    float* out_arc  = out + (size_t)2 * NN * TT;

    float *pX, *pXW, *pH0, *pGS, *pprobs;
    float *pWTih0g, *pWTih1g, *pWThead, *pWTdep;
    uint32_t *pBsw;
    cudaGetSymbolAddress((void**)&pX, d_X);
    cudaGetSymbolAddress((void**)&pXW, d_XW);
    cudaGetSymbolAddress((void**)&pH0, d_H0);
    cudaGetSymbolAddress((void**)&pGS, d_GS);
    cudaGetSymbolAddress((void**)&pprobs, d_probs);
    cudaGetSymbolAddress((void**)&pWTih0g, d_WT_ih0g);
    cudaGetSymbolAddress((void**)&pWTih1g, d_WT_ih1g);
    cudaGetSymbolAddress((void**)&pWThead, d_WT_head);
    cudaGetSymbolAddress((void**)&pWTdep, d_WT_dep);
    cudaGetSymbolAddress((void**)&pBsw, d_Bsw);

    cudaFuncSetAttribute(edge_mma_kernel,
                         cudaFuncAttributeMaxDynamicSharedMemorySize, EDGE_SMEM_BYTES);

    // launch 1: fused prep
    prep_kernel<<<dim3(4096, 6), 256>>>(
        input, sentinel, g_Wih0, g_Wih1, head_W, dep_W,
        e_Whh0, e_Wih1, e_Whh1,
        pX, pWTih0g, pWTih1g, pWThead, pWTdep, pBsw);

    // launches 2-5: g-RNN layers
    gemm_kernel<0><<<dim3(NN/64, HGH/64), 256>>>(pX, pWTih0g, g_bih0, g_bhh0, pXW, DD, HGH);
    scan_g_cluster<<<BB*4, 256>>>(pXW, g_Whh0, pH0, nullptr, 0);
    gemm_kernel<0><<<dim3(NN/64, HGH/64), 256>>>(pH0, pWTih1g, g_bih1, g_bhh1, pXW, HGH, HGH);
    scan_g_cluster<<<BB*4, 256>>>(pXW, g_Whh1, pGS, mask, 1);

    // launch 6: fused edge scan (bf16 mma.sync + ldmatrix fragments)
    edge_mma_kernel<<<NN/EROWS, 256, EDGE_SMEM_BYTES>>>(
        pGS, pBsw, e_Wih0, e_bih0, e_bhh0, e_bih1, e_bhh1,
        cls_W, cls_b, pprobs);

    // tags
    gemm_kernel<1><<<dim3(NN/64, TT/64), 256>>>(pGS, pWThead, head_b, nullptr, out_head, HGH, TT);
    gemm_kernel<1><<<dim3(NN/64, TT/64), 256>>>(pGS, pWTdep,  dep_b,  nullptr, out_dep,  HGH, TT);

    // arc_logits
    arc_kernel<<<dim3(SS, BB), SS>>>(pprobs, out_arc);
}

// round 13
// speedup vs baseline: 1.1143x; 1.0740x over previous
#include <cuda_runtime.h>
#include <cuda_bf16.h>
#include <math.h>
#include <stdint.h>

// Problem constants
#define BB   16
#define SS   512
#define SS0  511
#define DD   512
#define HGH  256
#define HEH  256
#define TT   128
#define MM   32
#define NN   (BB*SS)   // 8192

// Edge kernel geometry
#define EROWS 64               // rows per CTA -> 128 CTAs, 1 CTA/SM
#define AST   132              // state row stride (u32 words)
#define BSTW  296              // B chunk row stride (u32 words)
#define CHK2  32               // k2-rows per chunk (K=64)
#define CH_WORDS (CHK2*BSTW)   // 9472 u32 per chunk
#define CH_BYTES (CH_WORDS*4)  // 37888 B (multiple of 16)
#define NBUF  3

// ---------------- device scratch ----------------
__device__ float  d_X   [NN*DD];
__device__ float  d_XW  [NN*HGH];
__device__ float  d_H0  [NN*HGH];
__device__ float  d_GS  [NN*HGH];
__device__ float  d_probs[MM*NN];

__device__ float    d_WT_ih0g[DD*HGH];
__device__ float    d_WT_ih1g[HGH*HGH];
__device__ __align__(16) uint32_t d_Bsw[12*CH_WORDS];  // 12 packed bf16 B chunks
__device__ float    d_WT_head[HGH*TT];
__device__ float    d_WT_dep [HGH*TT];

// ---------------- helpers ----------------
__device__ __forceinline__ float fast_tanh(float x) {
    float y;
    asm("tanh.approx.f32 %0, %1;" : "=f"(y) : "f"(x));
    return y;
}

__device__ __forceinline__ void mma_bf16(float c[4], const uint32_t a[4],
                                         uint32_t b0, uint32_t b1) {
    asm volatile("mma.sync.aligned.m16n8k16.row.col.f32.bf16.bf16.f32 "
        "{%0,%1,%2,%3},{%4,%5,%6,%7},{%8,%9},{%0,%1,%2,%3};"
        : "+f"(c[0]), "+f"(c[1]), "+f"(c[2]), "+f"(c[3])
        : "r"(a[0]), "r"(a[1]), "r"(a[2]), "r"(a[3]), "r"(b0), "r"(b1));
}

__device__ __forceinline__ uint32_t pack_bf16x2(float lo, float hi) {
    __nv_bfloat162 v = __floats2bfloat162_rn(lo, hi);
    return *reinterpret_cast<uint32_t*>(&v);
}

__device__ __forceinline__ uint32_t smem_u32(const void* p) {
    return (uint32_t)__cvta_generic_to_shared(p);
}

#define MBAR_INIT(mb, c)  asm volatile("mbarrier.init.shared.b64 [%0], %1;" :: "r"(mb), "r"(c) : "memory")
#define MBWAIT(mb, par)   asm volatile("{\n\t.reg .pred P;\nMBW%=:\n\tmbarrier.try_wait.parity.acquire.cta.shared::cta.b64 P, [%0], %1;\n\t@!P bra MBW%=;\n\t}" :: "r"(mb), "r"(par) : "memory")
#define EXPECT_TX(mb, n)  asm volatile("mbarrier.arrive.expect_tx.shared.b64 _, [%0], %1;" :: "r"(mb), "r"(n) : "memory")

__device__ __forceinline__ void bulk_fill(uint32_t dst, const uint32_t* src, uint32_t mbar)
{
    asm volatile(
        "cp.async.bulk.shared::cluster.global.mbarrier::complete_tx::bytes [%0], [%1], %2, [%3];"
        :: "r"(dst), "l"(src), "r"((uint32_t)CH_BYTES), "r"(mbar) : "memory");
}

// ---------------- single fused prep kernel ----------------
__device__ __forceinline__ void prep_transpose(const float* __restrict__ in,
                                               float* __restrict__ out,
                                               int R, int C, int bx, int tid)
{
    int tilesC = C >> 5, tilesR = R >> 5;
    if (bx >= tilesC * tilesR) return;
    int c0 = (bx % tilesC) << 5;
    int r0 = (bx / tilesC) << 5;
    __shared__ float tile[32][33];
    int x = tid & 31, y = tid >> 5;
    #pragma unroll
    for (int dy = 0; dy < 32; dy += 8)
        tile[y + dy][x] = in[(size_t)(r0 + y + dy) * C + c0 + x];
    __syncthreads();
    #pragma unroll
    for (int dy = 0; dy < 32; dy += 8)
        out[(size_t)(c0 + y + dy) * R + r0 + x] = tile[x][y + dy];
}

__global__ void __launch_bounds__(256) prep_kernel(
    const float* __restrict__ input, const float* __restrict__ sent,
    const float* __restrict__ g_Wih0, const float* __restrict__ g_Wih1,
    const float* __restrict__ head_W, const float* __restrict__ dep_W,
    const float* __restrict__ e_Whh0, const float* __restrict__ e_Wih1,
    const float* __restrict__ e_Whh1,
    float* __restrict__ X,
    float* __restrict__ WTih0g, float* __restrict__ WTih1g,
    float* __restrict__ WThead, float* __restrict__ WTdep,
    uint32_t* __restrict__ Bsw)
{
    int task = blockIdx.y;
    int bx   = blockIdx.x;
    int tid  = threadIdx.x;
    if (task == 0) {
        int idx = bx * 256 + tid;
        int n  = idx >> 7;
        int k4 = idx & 127;
        int b = n >> 9, s = n & 511;
        float4 v;
        if (s == 0) v = ((const float4*)sent)[k4];
        else        v = ((const float4*)input)[(size_t)((b*SS0 + s - 1) << 7) + k4];
        ((float4*)X)[idx] = v;
    } else if (task == 1) {
        prep_transpose(g_Wih0, WTih0g, HGH, DD, bx, tid);
    } else if (task == 2) {
        prep_transpose(g_Wih1, WTih1g, HGH, HGH, bx, tid);
    } else if (task == 3) {
        prep_transpose(head_W, WThead, TT, HGH, bx, tid);
    } else if (task == 4) {
        prep_transpose(dep_W, WTdep, TT, HGH, bx, tid);
    } else {
        // pack e-weights: word(chunk, k2l, n) = chunk*CH_WORDS + k2l*BSTW + (n&7)*36 + (n>>3)
        // chunks (K=64 each): 0-3 Whh0 | 4-7 Wih1 | 8-11 Whh1
        if (bx >= 384) return;
        int idx = bx * 256 + tid;     // over 3*256*128
        int seg = idx >> 15;
        int rem = idx & 32767;
        int n  = rem >> 7;
        int k2 = rem & 127;
        const float* W = (seg == 0) ? e_Whh0 : (seg == 1) ? e_Wih1 : e_Whh1;
        float2 v = *(const float2*)&W[(size_t)n * 256 + (k2 << 1)];
        int chunk = seg * 4 + (k2 >> 5);
        int k2l = k2 & 31;
        Bsw[chunk * CH_WORDS + k2l * BSTW + (n & 7) * 36 + (n >> 3)] =
            pack_bf16x2(v.x, v.y);
    }
}

// ---------------- g-RNN recurrence: 4-CTA cluster per batch ----------------
__global__ void __launch_bounds__(256, 1) __cluster_dims__(4, 1, 1)
scan_g_cluster(const float* __restrict__ XW,
               const float* __restrict__ Whh,
               float* __restrict__ Hout,
               const int* __restrict__ mask, int applyMask)
{
    __shared__ float hs[2][272];
    __shared__ alignas(8) unsigned long long mbar[2];

    int tid  = threadIdx.x;
    int rank = blockIdx.x & 3;
    int b    = blockIdx.x >> 2;
    int jl   = tid >> 2;
    int q    = tid & 3;
    int j    = rank * 64 + jl;

    float w[64];
    {
        const float4* ws = (const float4*)(Whh + (size_t)j * 256 + q * 64);
        #pragma unroll
        for (int i = 0; i < 16; i++) {
            float4 v = ws[i];
            w[4*i+0] = v.x; w[4*i+1] = v.y; w[4*i+2] = v.z; w[4*i+3] = v.w;
        }
    }

    hs[0][tid] = 0.0f; hs[1][tid] = 0.0f;
    if (tid < 16) { hs[0][256 + tid] = 0.0f; hs[1][256 + tid] = 0.0f; }

    uint32_t mbar_l[2] = { smem_u32(&mbar[0]), smem_u32(&mbar[1]) };
    if (tid == 0) {
        MBAR_INIT(mbar_l[0], 1);
        MBAR_INIT(mbar_l[1], 1);
    }
    __syncthreads();
    asm volatile("barrier.cluster.arrive.aligned;" ::: "memory");
    asm volatile("barrier.cluster.wait.aligned;"   ::: "memory");

    uint32_t rdata[2][4], rbar[2][4];
    if (q == 0) {
        uint32_t off = (uint32_t)(rank * 68 + jl) * 4u;
        uint32_t l0 = smem_u32(hs[0]) + off;
        uint32_t l1 = smem_u32(hs[1]) + off;
        #pragma unroll
        for (int c = 0; c < 4; c++) {
            asm("mapa.shared::cluster.u32 %0, %1, %2;" : "=r"(rdata[0][c]) : "r"(l0), "r"(c));
            asm("mapa.shared::cluster.u32 %0, %1, %2;" : "=r"(rdata[1][c]) : "r"(l1), "r"(c));
            asm("mapa.shared::cluster.u32 %0, %1, %2;" : "=r"(rbar[0][c]) : "r"(mbar_l[0]), "r"(c));
            asm("mapa.shared::cluster.u32 %0, %1, %2;" : "=r"(rbar[1][c]) : "r"(mbar_l[1]), "r"(c));
        }
    }

    float xw_cur = (q == 0) ? XW[(size_t)(b * SS) * 256 + j] : 0.0f;
    float mf_cur = 1.0f;
    int cur = 0;

    for (int t = 0; t < SS; t++) {
        float xw_next = 0.0f, mf_next = 1.0f;
        if (q == 0 && t + 1 < SS) {
            xw_next = XW[(size_t)(b * SS + t + 1) * 256 + j];
            if (applyMask) mf_next = (float)mask[b * SS0 + t];
        }

        const float4* hq = (const float4*)(hs[cur] + q * 68);
        float a0 = 0.0f, a1 = 0.0f, a2 = 0.0f, a3 = 0.0f;
        #pragma unroll
        for (int i = 0; i < 16; i++) {
            float4 h = hq[i];
            a0 = fmaf(w[4*i+0], h.x, a0);
            a1 = fmaf(w[4*i+1], h.y, a1);
            a2 = fmaf(w[4*i+2], h.z, a2);
            a3 = fmaf(w[4*i+3], h.w, a3);
        }
        float s = (a0 + a1) + (a2 + a3);
        s += __shfl_xor_sync(0xFFFFFFFFu, s, 1);
        s += __shfl_xor_sync(0xFFFFFFFFu, s, 2);

        float hn = 0.0f;
        if (q == 0) {
            hn = fast_tanh(xw_cur + s);
            Hout[(size_t)(b * SS + t) * 256 + j] = hn * mf_cur;
        }

        __syncthreads();

        int nb = t & 1;
        if (q == 0) {
            uint32_t hv = __float_as_uint(hn);
            #pragma unroll
            for (int c = 0; c < 4; c++) {
                asm volatile(
                    "st.async.shared::cluster.mbarrier::complete_tx::bytes.b32 [%0], %1, [%2];"
                    :: "r"(rdata[cur ^ 1][c]), "r"(hv), "r"(rbar[nb][c]) : "memory");
            }
        }
        if (tid == 0) {
            asm volatile(
                "mbarrier.arrive.expect_tx.release.cluster.shared::cta.b64 _, [%0], 1024;"
                :: "r"(mbar_l[nb]) : "memory");
        }
        {
            uint32_t par = (t >> 1) & 1;
            asm volatile(
                "{\n\t.reg .pred P1;\n"
                "WAITLP_%=:\n\t"
                "mbarrier.try_wait.parity.acquire.cluster.shared::cta.b64 P1, [%0], %1;\n\t"
                "@!P1 bra WAITLP_%=;\n\t}"
                :: "r"(mbar_l[nb]), "r"(par) : "memory");
        }

        xw_cur = xw_next;
        mf_cur = mf_next;
        cur ^= 1;
    }
}

// ---------------- generic tiled SIMT GEMM (input proj + tags) ----------------
__device__ __forceinline__ void gemm_tile_loop(const float* __restrict__ A,
                                               const float* __restrict__ B,
                                               int K, int J, int n0, int j0, int tid,
                                               float acc[4][4],
                                               float (*As)[64], float (*Bs)[64])
{
    int tx = tid & 15, ty = tid >> 4;
    for (int k0 = 0; k0 < K; k0 += 16) {
        __syncthreads();
        {
            int row = tid >> 2;
            int kb  = (tid & 3) << 2;
            float4 av = *(const float4*)&A[(size_t)(n0 + row) * K + k0 + kb];
            As[kb + 0][row] = av.x;
            As[kb + 1][row] = av.y;
            As[kb + 2][row] = av.z;
            As[kb + 3][row] = av.w;
        }
        {
            int row = tid >> 4;
            int cb  = (tid & 15) << 2;
            *(float4*)&Bs[row][cb] = *(const float4*)&B[(size_t)(k0 + row) * J + j0 + cb];
        }
        __syncthreads();
        #pragma unroll
        for (int kk = 0; kk < 16; kk++) {
            float4 a = *(const float4*)&As[kk][ty << 2];
            float4 b = *(const float4*)&Bs[kk][tx << 2];
            acc[0][0] = fmaf(a.x, b.x, acc[0][0]);
            acc[0][1] = fmaf(a.x, b.y, acc[0][1]);
            acc[0][2] = fmaf(a.x, b.z, acc[0][2]);
            acc[0][3] = fmaf(a.x, b.w, acc[0][3]);
            acc[1][0] = fmaf(a.y, b.x, acc[1][0]);
            acc[1][1] = fmaf(a.y, b.y, acc[1][1]);
            acc[1][2] = fmaf(a.y, b.z, acc[1][2]);
            acc[1][3] = fmaf(a.y, b.w, acc[1][3]);
            acc[2][0] = fmaf(a.z, b.x, acc[2][0]);
            acc[2][1] = fmaf(a.z, b.y, acc[2][1]);
            acc[2][2] = fmaf(a.z, b.z, acc[2][2]);
            acc[2][3] = fmaf(a.z, b.w, acc[2][3]);
            acc[3][0] = fmaf(a.w, b.x, acc[3][0]);
            acc[3][1] = fmaf(a.w, b.y, acc[3][1]);
            acc[3][2] = fmaf(a.w, b.z, acc[3][2]);
            acc[3][3] = fmaf(a.w, b.w, acc[3][3]);
        }
    }
}

// EPI: 0 = +b1+b2 ; 1 = elu(+b1)
template<int EPI>
__global__ void __launch_bounds__(256) gemm_kernel(const float* __restrict__ A,
                                                   const float* __restrict__ B,
                                                   const float* __restrict__ b1,
                                                   const float* __restrict__ b2,
                                                   float* __restrict__ C,
                                                   int K, int J)
{
    __shared__ float As[16][64];
    __shared__ float Bs[16][64];
    int tid = threadIdx.x;
    int n0 = blockIdx.x * 64;
    int j0 = blockIdx.y * 64;
    float acc[4][4] = {};
    gemm_tile_loop(A, B, K, J, n0, j0, tid, acc, As, Bs);

    int tx = tid & 15, ty = tid >> 4;
    int j_base = j0 + (tx << 2);
    #pragma unroll
    for (int i = 0; i < 4; i++) {
        int n = n0 + (ty << 2) + i;
        float r[4];
        #pragma unroll
        for (int l = 0; l < 4; l++) {
            int j = j_base + l;
            float x = acc[i][l];
            if (EPI == 0) {
                x += b1[j] + b2[j];
            } else {
                x += b1[j];
                x = (x > 0.0f) ? x : expm1f(x);
            }
            r[l] = x;
        }
        *(float4*)&C[(size_t)n * J + j_base] = make_float4(r[0], r[1], r[2], r[3]);
    }
}

// ---------------- fused edge scan: bf16 mma.sync + cp.async.bulk B stream ----
// One GEMM pass: nch K=64 chunks; A from hA0 (first n0ch) then hA1.
__device__ __forceinline__ void edge_pass(
    uint32_t bB, const uint32_t* __restrict__ Bg, int nch,
    const uint32_t* __restrict__ hA0, const uint32_t* __restrict__ hA1, int n0ch,
    float acc[2][8][4], int rg, int cg, int lane, int tid,
    const uint32_t* mb, uint32_t& phase)
{
    // prologue fills
    if (tid == 0) {
        int npre = (nch < NBUF) ? nch : NBUF;
        for (int c = 0; c < npre; c++) {
            EXPECT_TX(mb[c], (uint32_t)CH_BYTES);
            bulk_fill(bB + (uint32_t)c * CH_BYTES, Bg + c * CH_WORDS, mb[c]);
        }
    }

    int m4 = lane >> 3;          // ldmatrix matrix index
    int rr = lane & 7;
    int gid = lane >> 2, tig = lane & 3;
    uint32_t rowoff[2];
    #pragma unroll
    for (int mt = 0; mt < 2; mt++) {
        int row = rg * 32 + mt * 16 + (m4 & 1) * 8 + rr;
        rowoff[mt] = (uint32_t)(row * AST + (m4 >> 1) * 4) * 4u;
    }

    #pragma unroll 1
    for (int c = 0; c < nch; c++) {
        int b = c % NBUF;
        MBWAIT(mb[b], (phase >> b) & 1);
        phase ^= 1u << b;

        const uint32_t* hA = (c < n0ch) ? hA0 : hA1;
        uint32_t hBase = smem_u32(hA) + (uint32_t)(((c < n0ch) ? c : c - n0ch) * 32) * 4u;
        uint32_t Bbb = bB + (uint32_t)b * CH_BYTES;

        #pragma unroll
        for (int s = 0; s < 4; s++) {
            uint32_t a[2][4];
            #pragma unroll
            for (int mt = 0; mt < 2; mt++) {
                uint32_t addr = hBase + rowoff[mt] + (uint32_t)(s * 8) * 4u;
                asm volatile("ldmatrix.sync.aligned.m8n8.x4.shared.b16 {%0,%1,%2,%3}, [%4];"
                    : "=r"(a[mt][0]), "=r"(a[mt][1]), "=r"(a[mt][2]), "=r"(a[mt][3])
                    : "r"(addr));
            }
            uint32_t b0addr = Bbb + (uint32_t)((s*8 + tig)     * BSTW + gid * 36 + cg * 8) * 4u;
            uint32_t b1addr = Bbb + (uint32_t)((s*8 + tig + 4) * BSTW + gid * 36 + cg * 8) * 4u;
            uint32_t b0a[8], b1a[8];
            asm volatile("ld.shared.v4.b32 {%0,%1,%2,%3}, [%4];"
                : "=r"(b0a[0]), "=r"(b0a[1]), "=r"(b0a[2]), "=r"(b0a[3]) : "r"(b0addr));
            asm volatile("ld.shared.v4.b32 {%0,%1,%2,%3}, [%4];"
                : "=r"(b0a[4]), "=r"(b0a[5]), "=r"(b0a[6]), "=r"(b0a[7]) : "r"(b0addr + 16u));
            asm volatile("ld.shared.v4.b32 {%0,%1,%2,%3}, [%4];"
                : "=r"(b1a[0]), "=r"(b1a[1]), "=r"(b1a[2]), "=r"(b1a[3]) : "r"(b1addr));
            asm volatile("ld.shared.v4.b32 {%0,%1,%2,%3}, [%4];"
                : "=r"(b1a[4]), "=r"(b1a[5]), "=r"(b1a[6]), "=r"(b1a[7]) : "r"(b1addr + 16u));
            #pragma unroll
            for (int nt = 0; nt < 8; nt++) {
                mma_bf16(acc[0][nt], a[0], b0a[nt], b1a[nt]);
                mma_bf16(acc[1][nt], a[1], b0a[nt], b1a[nt]);
            }
        }

        __syncthreads();   // all warps done with buffer b
        if (tid == 0 && c + NBUF < nch) {
            EXPECT_TX(mb[b], (uint32_t)CH_BYTES);
            bulk_fill(bB + (uint32_t)b * CH_BYTES, Bg + (c + NBUF) * CH_WORDS, mb[b]);
        }
    }
}

__global__ void __launch_bounds__(256, 1) edge_mma_kernel(
    const float* __restrict__ gs,
    const uint32_t* __restrict__ Bsw,       // 12 chunks
    const float* __restrict__ w0,
    const float* __restrict__ bih0, const float* __restrict__ bhh0,
    const float* __restrict__ bih1, const float* __restrict__ bhh1,
    const float* __restrict__ clsW, const float* __restrict__ clsb,
    float* __restrict__ probs)
{
    extern __shared__ uint32_t dyn[];
    uint32_t* Bbuf = dyn;                      // NBUF * CH_WORDS (16B aligned)
    uint32_t* hs0  = Bbuf + NBUF * CH_WORDS;   // 64*AST
    uint32_t* hs1  = hs0 + EROWS * AST;
    float* w0s = (float*)(hs1 + EROWS * AST);  // 256
    float* bc0 = w0s + 256;
    float* bc1 = bc0 + 256;
    float* clw = bc1 + 256;
    float* ps  = clw + 256;                    // 64
    __shared__ alignas(8) unsigned long long mbar_s[NBUF];
    __shared__ float s_clsb;

    int tid = threadIdx.x;
    int lane = tid & 31, warp = tid >> 5;
    int gid = lane >> 2, tig = lane & 3;
    int rg = warp >> 2, cg = warp & 3;
    int n0 = blockIdx.x * EROWS;

    uint32_t mb[NBUF];
    #pragma unroll
    for (int i = 0; i < NBUF; i++) mb[i] = smem_u32(&mbar_s[i]);
    if (tid == 0) {
        #pragma unroll
        for (int i = 0; i < NBUF; i++) MBAR_INIT(mb[i], 1);
        s_clsb = clsb[0];
    }

    w0s[tid] = w0[tid];
    bc0[tid] = bih0[tid] + bhh0[tid];
    bc1[tid] = bih1[tid] + bhh1[tid];
    clw[tid] = clsW[tid];

    // init: h0 = bf16(gs rows), h1 = 0, p = 1
    for (int i = tid; i < EROWS * 128; i += 256) {
        int r = i >> 7, c2 = i & 127;
        float2 v = *(const float2*)&gs[(size_t)(n0 + r) * 256 + (c2 << 1)];
        hs0[r * AST + c2] = pack_bf16x2(v.x, v.y);
        hs1[r * AST + c2] = 0u;
    }
    if (tid < EROWS) ps[tid] = 1.0f;
    __syncthreads();

    float acc[2][8][4];
    uint32_t phase = 0;

    for (int m = 0; m < MM; m++) {
        // ---- GEMM1: acc = h0 @ Whh0^T (chunks 0-3) ----
        #pragma unroll
        for (int mt = 0; mt < 2; mt++)
            #pragma unroll
            for (int nt = 0; nt < 8; nt++)
                #pragma unroll
                for (int q = 0; q < 4; q++) acc[mt][nt][q] = 0.0f;

        edge_pass(smem_u32(Bbuf), Bsw, 4, hs0, hs0, 4, acc, rg, cg, lane, tid, mb, phase);
        __syncthreads();

        // epilogue1: h0 = tanh(acc + p*w0 + bc0)
        #pragma unroll
        for (int mt = 0; mt < 2; mt++) {
            int r0 = rg * 32 + mt * 16 + gid;
            int r1 = r0 + 8;
            float p0 = ps[r0], p1 = ps[r1];
            #pragma unroll
            for (int nt = 0; nt < 8; nt++) {
                int cb = cg * 64 + nt * 8 + tig * 2;
                float x0 = acc[mt][nt][0] + p0 * w0s[cb]     + bc0[cb];
                float x1 = acc[mt][nt][1] + p0 * w0s[cb + 1] + bc0[cb + 1];
                float x2 = acc[mt][nt][2] + p1 * w0s[cb]     + bc0[cb];
                float x3 = acc[mt][nt][3] + p1 * w0s[cb + 1] + bc0[cb + 1];
                hs0[r0 * AST + (cb >> 1)] = pack_bf16x2(fast_tanh(x0), fast_tanh(x1));
                hs0[r1 * AST + (cb >> 1)] = pack_bf16x2(fast_tanh(x2), fast_tanh(x3));
            }
        }
        __syncthreads();

        // ---- GEMM2: acc = h0_new @ Wih1^T (+ h1 @ Whh1^T when m>0) ----
        #pragma unroll
        for (int mt = 0; mt < 2; mt++)
            #pragma unroll
            for (int nt = 0; nt < 8; nt++)
                #pragma unroll
                for (int q = 0; q < 4; q++) acc[mt][nt][q] = 0.0f;

        int nch2 = (m == 0) ? 4 : 8;
        edge_pass(smem_u32(Bbuf), Bsw + 4 * CH_WORDS, nch2, hs0, hs1, 4, acc, rg, cg, lane, tid, mb, phase);
        __syncthreads();

        // epilogue2: h1 = tanh(acc + bc1)
        #pragma unroll
        for (int mt = 0; mt < 2; mt++) {
            int r0 = rg * 32 + mt * 16 + gid;
            int r1 = r0 + 8;
            #pragma unroll
            for (int nt = 0; nt < 8; nt++) {
                int cb = cg * 64 + nt * 8 + tig * 2;
                float x0 = acc[mt][nt][0] + bc1[cb];
                float x1 = acc[mt][nt][1] + bc1[cb + 1];
                float x2 = acc[mt][nt][2] + bc1[cb];
                float x3 = acc[mt][nt][3] + bc1[cb + 1];
                hs1[r0 * AST + (cb >> 1)] = pack_bf16x2(fast_tanh(x0), fast_tanh(x1));
                hs1[r1 * AST + (cb >> 1)] = pack_bf16x2(fast_tanh(x2), fast_tanh(x3));
            }
        }
        __syncthreads();

        // ---- p = sigmoid(h1 . clsW + clsb); each warp owns 8 rows ----
        #pragma unroll
        for (int i = 0; i < 8; i++) {
            int r = warp * 8 + i;
            float s = 0.0f;
            #pragma unroll
            for (int k = 0; k < 4; k++) {
                int c2 = lane + k * 32;
                __nv_bfloat162 bv = *reinterpret_cast<const __nv_bfloat162*>(&hs1[r * AST + c2]);
                float2 fv = __bfloat1622float2(bv);
                s = fmaf(fv.x, clw[c2 * 2], fmaf(fv.y, clw[c2 * 2 + 1], s));
            }
            #pragma unroll
            for (int o = 16; o; o >>= 1) s += __shfl_xor_sync(0xFFFFFFFFu, s, o);
            if (lane == 0) {
                float p = 1.0f / (1.0f + expf(-(s + s_clsb)));
                ps[r] = p;
                probs[(size_t)m * NN + n0 + r] = p;
            }
        }
        __syncthreads();
    }
}

// ---------------- arc_logits assembly ----------------
__global__ void arc_kernel(const float* __restrict__ probs, float* __restrict__ arc)
{
    int j = blockIdx.x;
    int b = blockIdx.y;
    int i = threadIdx.x;
    int start = (i - MM > 0) ? (i - MM) : 0;
    float v = 0.0f;
    if (j >= start && j < i) {
        int midx = j - start;
        v = probs[(size_t)midx * NN + b * SS + i];
    }
    arc[(size_t)(b * SS + j) * SS + i] = v;
}

// ---------------- host orchestration ----------------
static const int EDGE_SMEM_BYTES =
    (NBUF * CH_WORDS + 2 * EROWS * AST) * 4 + (4 * 256 + EROWS) * 4 + 256;

extern "C" void kernel_launch(void* const* d_in, const int* in_sizes, int n_in,
                              void* d_out, int out_size)
{
    const float* input   = (const float*)d_in[0];
    const float* sentinel= (const float*)d_in[1];
    const float* g_Wih0  = (const float*)d_in[2];
    const float* g_Whh0  = (const float*)d_in[3];
    const float* g_bih0  = (const float*)d_in[4];
    const float* g_bhh0  = (const float*)d_in[5];
    const float* g_Wih1  = (const float*)d_in[6];
    const float* g_Whh1  = (const float*)d_in[7];
    const float* g_bih1  = (const float*)d_in[8];
    const float* g_bhh1  = (const float*)d_in[9];
    const float* e_Wih0  = (const float*)d_in[10];
    const float* e_Whh0  = (const float*)d_in[11];
    const float* e_bih0  = (const float*)d_in[12];
    const float* e_bhh0  = (const float*)d_in[13];
    const float* e_Wih1  = (const float*)d_in[14];
    const float* e_Whh1  = (const float*)d_in[15];
    const float* e_bih1  = (const float*)d_in[16];
    const float* e_bhh1  = (const float*)d_in[17];
    const float* cls_W   = (const float*)d_in[18];
    const float* cls_b   = (const float*)d_in[19];
    const float* head_W  = (const float*)d_in[20];
    const float* head_b  = (const float*)d_in[21];
    const float* dep_W   = (const float*)d_in[22];
    const float* dep_b   = (const float*)d_in[23];
    const int*   mask    = (const int*)  d_in[24];
    (void)in_sizes; (void)n_in; (void)out_size;

    float* out = (float*)d_out;
    float* out_head = out;
    float* out_dep  = out + (size_t)NN * TT;
    float* out_arc  = out + (size_t)2 * NN * TT;

    float *pX, *pXW, *pH0, *pGS, *pprobs;
    float *pWTih0g, *pWTih1g, *pWThead, *pWTdep;
    uint32_t *pBsw;
    cudaGetSymbolAddress((void**)&pX, d_X);
    cudaGetSymbolAddress((void**)&pXW, d_XW);
    cudaGetSymbolAddress((void**)&pH0, d_H0);
    cudaGetSymbolAddress((void**)&pGS, d_GS);
    cudaGetSymbolAddress((void**)&pprobs, d_probs);
    cudaGetSymbolAddress((void**)&pWTih0g, d_WT_ih0g);
    cudaGetSymbolAddress((void**)&pWTih1g, d_WT_ih1g);
    cudaGetSymbolAddress((void**)&pWThead, d_WT_head);
    cudaGetSymbolAddress((void**)&pWTdep, d_WT_dep);
    cudaGetSymbolAddress((void**)&pBsw, d_Bsw);

    cudaFuncSetAttribute(edge_mma_kernel,
                         cudaFuncAttributeMaxDynamicSharedMemorySize, EDGE_SMEM_BYTES);

    // launch 1: fused prep
    prep_kernel<<<dim3(4096, 6), 256>>>(
        input, sentinel, g_Wih0, g_Wih1, head_W, dep_W,
        e_Whh0, e_Wih1, e_Whh1,
        pX, pWTih0g, pWTih1g, pWThead, pWTdep, pBsw);

    // launches 2-5: g-RNN layers
    gemm_kernel<0><<<dim3(NN/64, HGH/64), 256>>>(pX, pWTih0g, g_bih0, g_bhh0, pXW, DD, HGH);
    scan_g_cluster<<<BB*4, 256>>>(pXW, g_Whh0, pH0, nullptr, 0);
    gemm_kernel<0><<<dim3(NN/64, HGH/64), 256>>>(pH0, pWTih1g, g_bih1, g_bhh1, pXW, HGH, HGH);
    scan_g_cluster<<<BB*4, 256>>>(pXW, g_Whh1, pGS, mask, 1);

    // launch 6: fused edge scan (bf16 mma.sync + cp.async.bulk weights)
    edge_mma_kernel<<<NN/EROWS, 256, EDGE_SMEM_BYTES>>>(
        pGS, pBsw, e_Wih0, e_bih0, e_bhh0, e_bih1, e_bhh1,
        cls_W, cls_b, pprobs);

    // tags
    gemm_kernel<1><<<dim3(NN/64, TT/64), 256>>>(pGS, pWThead, head_b, nullptr, out_head, HGH, TT);
    gemm_kernel<1><<<dim3(NN/64, TT/64), 256>>>(pGS, pWTdep,  dep_b,  nullptr, out_dep,  HGH, TT);

    // arc_logits
    arc_kernel<<<dim3(SS, BB), SS>>>(pprobs, out_arc);
}